// round 13
// baseline (speedup 1.0000x reference)
#include <cuda_runtime.h>
#include <cstdint>

// LineSpectralPairsStabilityCheck: (256, 4096, 33) fp32, 1,048,576 rows.
// Per row: keep [0]; 4 passes of {31-step neighbor-separation scan + clip}.
// Warp-decoupled TMA bulk staging: each warp owns a contiguous 4224B chunk
// (32 rows x 33 floats), with its own mbarrier + cp.async.bulk in and its
// own bulk store out. No block barriers -> no intra-CTA convoy; warps start
// computing the moment their own chunk lands and destage independently.

#define W 33
#define THREADS 128
#define ROWS_PER_BLOCK 128
#define TILE_ELEMS (ROWS_PER_BLOCK * W)   // 4224 floats
#define WCHUNK_ELEMS (32 * W)             // 1056 floats per warp
#define WCHUNK_BYTES (WCHUNK_ELEMS * 4)   // 4224 B (16B-multiple)

__global__ void __launch_bounds__(THREADS)
lsp_stability_kernel(const float* __restrict__ in, float* __restrict__ out)
{
    __shared__ alignas(128) float sm[TILE_ELEMS];
    __shared__ alignas(8) unsigned long long mbar[4];

    const int t    = threadIdx.x;
    const int warp = t >> 5;
    const int lane = t & 31;

    const long long gchunk = (long long)blockIdx.x * TILE_ELEMS + warp * WCHUNK_ELEMS;

    uint32_t sm_addr, mbar_addr;
    asm("{ .reg .u64 u; cvta.to.shared.u64 u, %1; cvt.u32.u64 %0, u; }"
        : "=r"(sm_addr) : "l"((void*)(sm + warp * WCHUNK_ELEMS)));
    asm("{ .reg .u64 u; cvta.to.shared.u64 u, %1; cvt.u32.u64 %0, u; }"
        : "=r"(mbar_addr) : "l"((void*)&mbar[warp]));

    // ---- warp-local: init mbarrier, launch this warp's bulk G->S copy ----
    if (lane == 0) {
        asm volatile("mbarrier.init.shared.b64 [%0], 1;" :: "r"(mbar_addr) : "memory");
    }
    __syncwarp();
    if (lane == 0) {
        asm volatile("mbarrier.arrive.expect_tx.shared.b64 _, [%0], %1;"
                     :: "r"(mbar_addr), "r"((uint32_t)WCHUNK_BYTES) : "memory");
        asm volatile("cp.async.bulk.shared::cta.global.mbarrier::complete_tx::bytes "
                     "[%0], [%1], %2, [%3];"
                     :: "r"(sm_addr), "l"(in + gchunk), "r"((uint32_t)WCHUNK_BYTES),
                        "r"(mbar_addr) : "memory");
    }
    // ---- this warp waits only on its own chunk (parity 0, one-shot) ----
    asm volatile(
        "{\n\t"
        ".reg .pred P1;\n\t"
        "WAIT_LOOP_%=:\n\t"
        "mbarrier.try_wait.parity.acquire.cta.shared::cta.b64 P1, [%0], 0, 0x989680;\n\t"
        "@P1 bra.uni WAIT_DONE_%=;\n\t"
        "bra.uni WAIT_LOOP_%=;\n\t"
        "WAIT_DONE_%=:\n\t"
        "}"
        :: "r"(mbar_addr) : "memory");

    // ---- lane owns one row: stride-33 smem, conflict-free ----
    // Channel 0 (K) passes through smem untouched.
    const int rbase = t * W;
    float v[W];   // v[0] unused
    #pragma unroll
    for (int i = 1; i < W; i++)
        v[i] = sm[rbase + i];

    const float pi_f  = 3.14159265358979323846f;
    const float min_d = 0.01f * pi_f / 33.0f;   // RATE * pi / (LSP_ORDER + 1)
    const float hi    = pi_f - min_d;

    #pragma unroll
    for (int it = 0; it < 4; it++) {
        // chain per step: u = c + m (FADD) -> s = max(u,0) (FMNMX)
        //              -> c = fma(s, 0.5, nxt) (FFMA); rest off-chain.
        float c = v[1];
        #pragma unroll
        for (int i = 2; i <= 32; i++) {
            float nxt = v[i];
            float m = min_d - nxt;            // off-chain
            float u = c + m;                  // chain
            float s = fmaxf(u, 0.0f);         // chain
            float o = fmaf(s, -0.5f, c);      // off-chain output
            o = fmaxf(o, min_d);
            v[i - 1] = fminf(o, hi);
            c = fmaf(s, 0.5f, nxt);           // chain (carried unclipped)
        }
        v[32] = fminf(fmaxf(c, min_d), hi);
    }

    // ---- write row back to its private smem cell ----
    #pragma unroll
    for (int i = 1; i < W; i++)
        sm[rbase + i] = v[i];
    __syncwarp();

    // ---- warp-local bulk S->G store of this warp's chunk ----
    if (lane == 0) {
        asm volatile("fence.proxy.async.shared::cta;" ::: "memory");
        asm volatile("cp.async.bulk.global.shared::cta.bulk_group [%0], [%1], %2;"
                     :: "l"(out + gchunk), "r"(sm_addr), "r"((uint32_t)WCHUNK_BYTES)
                     : "memory");
        asm volatile("cp.async.bulk.commit_group;" ::: "memory");
        asm volatile("cp.async.bulk.wait_group 0;" ::: "memory");
    }
}

extern "C" void kernel_launch(void* const* d_in, const int* in_sizes, int n_in,
                              void* d_out, int out_size)
{
    const float* in = (const float*)d_in[0];
    float* out = (float*)d_out;

    const int total = in_sizes[0];            // 256*4096*33 = 34,603,008
    const int rows = total / W;               // 1,048,576
    const int blocks = rows / ROWS_PER_BLOCK; // 8192 (exact)

    lsp_stability_kernel<<<blocks, THREADS>>>(in, out);
}